// round 1
// baseline (speedup 1.0000x reference)
#include <cuda_runtime.h>
#include <float.h>

// Problem constants (fixed shapes per reference)
#define BATCH   32
#define TLEN    2048
#define FDIM    512
#define UDIM    128
#define KSEL    64
#define NFRAMES (BATCH * TLEN)     // 65536
#define NEG_BIG -1.0e9f

// Scratch (no allocations allowed in kernel_launch)
__device__ float         g_scores[NFRAMES];
__device__ unsigned char g_sel[NFRAMES];

// ---------------------------------------------------------------------------
// Kernel A: fused score GEMM.
// Tile: M=64 frames, N=128 (all of U), K chunks of 32. 256 threads,
// each computes a 4x8 sub-tile of h = x@W1, then epilogue does
// relu(h + b1) . W2 reduced across the 16 lanes sharing the same rows.
// Also computes the "any feature nonzero" mask while loading x.
// ---------------------------------------------------------------------------
__global__ __launch_bounds__(256, 2)
void score_kernel(const float* __restrict__ x,
                  const float* __restrict__ W1,
                  const float* __restrict__ b1,
                  const float* __restrict__ W2,
                  const float* __restrict__ b2)
{
    __shared__ float As[64][33];      // [m][k], padded: conflict-free stores & broadcast loads
    __shared__ float Bs[32][128];     // [k][n]
    __shared__ float s_b1[UDIM];
    __shared__ float s_W2[UDIM];
    __shared__ int   rowNZ[64];

    const int tid = threadIdx.x;
    const int tx  = tid & 15;         // N direction: 16 threads cover 128 cols (8 each)
    const int ty  = tid >> 4;         // M direction: 16 groups cover 64 rows (4 each)
    const int frame0 = blockIdx.x * 64;

    if (tid < UDIM) {
        s_b1[tid] = b1[tid];
        s_W2[tid] = W2[tid];
    }
    if (tid < 64) rowNZ[tid] = 0;

    // x-tile load mapping: 64 rows x 32 k-cols, 256 threads -> 8 floats each
    const int lm = tid >> 2;          // row 0..63
    const int lk = (tid & 3) * 8;     // k offset 0..24

    float acc[4][8];
    #pragma unroll
    for (int i = 0; i < 4; i++)
        #pragma unroll
        for (int j = 0; j < 8; j++)
            acc[i][j] = 0.0f;

    __syncthreads();

    for (int kc = 0; kc < FDIM; kc += 32) {
        // --- load x tile (and nonzero mask) ---
        const float4* xr = (const float4*)(x + (size_t)(frame0 + lm) * FDIM + kc + lk);
        float4 v0 = xr[0];
        float4 v1 = xr[1];
        bool nz = (v0.x != 0.f) | (v0.y != 0.f) | (v0.z != 0.f) | (v0.w != 0.f) |
                  (v1.x != 0.f) | (v1.y != 0.f) | (v1.z != 0.f) | (v1.w != 0.f);
        if (nz) rowNZ[lm] = 1;        // benign race: all writers store 1
        As[lm][lk + 0] = v0.x; As[lm][lk + 1] = v0.y;
        As[lm][lk + 2] = v0.z; As[lm][lk + 3] = v0.w;
        As[lm][lk + 4] = v1.x; As[lm][lk + 5] = v1.y;
        As[lm][lk + 6] = v1.z; As[lm][lk + 7] = v1.w;

        // --- load W1 chunk: 32 x 128 floats = 1024 float4s ---
        #pragma unroll
        for (int i = 0; i < 4; i++) {
            int v = tid + i * 256;            // float4 index
            int kk = v >> 5;                  // 128 floats = 32 float4 per row
            int n4 = v & 31;
            float4 w = *(const float4*)(W1 + (size_t)(kc + kk) * UDIM + n4 * 4);
            *(float4*)(&Bs[kk][n4 * 4]) = w;
        }
        __syncthreads();

        // --- compute ---
        #pragma unroll 8
        for (int kk = 0; kk < 32; kk++) {
            float a[4];
            #pragma unroll
            for (int i = 0; i < 4; i++) a[i] = As[ty * 4 + i][kk];
            float4 bA = *(const float4*)(&Bs[kk][tx * 8]);
            float4 bB = *(const float4*)(&Bs[kk][tx * 8 + 4]);
            float bb[8] = {bA.x, bA.y, bA.z, bA.w, bB.x, bB.y, bB.z, bB.w};
            #pragma unroll
            for (int i = 0; i < 4; i++)
                #pragma unroll
                for (int j = 0; j < 8; j++)
                    acc[i][j] = fmaf(a[i], bb[j], acc[i][j]);
        }
        __syncthreads();
    }

    // --- epilogue: score[row] = sum_u relu(h + b1[u]) * W2[u] + b2 ---
    const float bias2 = b2[0];
    #pragma unroll
    for (int i = 0; i < 4; i++) {
        float partial = 0.0f;
        #pragma unroll
        for (int j = 0; j < 8; j++) {
            int n = tx * 8 + j;
            float h = acc[i][j] + s_b1[n];
            h = fmaxf(h, 0.0f);
            partial = fmaf(h, s_W2[n], partial);
        }
        // reduce across the 16 lanes (same ty) partitioning the 128 cols
        #pragma unroll
        for (int off = 8; off >= 1; off >>= 1)
            partial += __shfl_xor_sync(0xffffffffu, partial, off, 16);
        if (tx == 0) {
            int row = ty * 4 + i;
            float s = partial + bias2;
            if (!rowNZ[row]) s = NEG_BIG;
            g_scores[frame0 + row] = s;
        }
    }
}

// ---------------------------------------------------------------------------
// Kernel B: per-batch top-64 via 64 stable argmax passes (lowest-index ties,
// matching jax.lax.top_k's selected set). One block per batch row.
// ---------------------------------------------------------------------------
__global__ __launch_bounds__(256)
void topk_kernel()
{
    __shared__ float vals[TLEN];
    __shared__ float rv[256];
    __shared__ int   ri[256];

    const int b   = blockIdx.x;
    const int tid = threadIdx.x;
    const int base = b * TLEN;

    for (int i = tid; i < TLEN; i += 256) {
        vals[i] = g_scores[base + i];
        g_sel[base + i] = 0;
    }
    __syncthreads();

    for (int iter = 0; iter < KSEL; iter++) {
        float best = -FLT_MAX;
        int   bi   = TLEN;
        for (int i = tid; i < TLEN; i += 256) {
            float v = vals[i];
            if (v > best) { best = v; bi = i; }     // strided scan: first hit is lowest idx
        }
        rv[tid] = best; ri[tid] = bi;
        __syncthreads();
        #pragma unroll
        for (int s = 128; s >= 1; s >>= 1) {
            if (tid < s) {
                float ov = rv[tid + s]; int oi = ri[tid + s];
                if (ov > rv[tid] || (ov == rv[tid] && oi < ri[tid])) {
                    rv[tid] = ov; ri[tid] = oi;
                }
            }
            __syncthreads();
        }
        if (tid == 0) {
            int sel = ri[0];
            vals[sel] = -FLT_MAX;
            g_sel[base + sel] = 1;
        }
        __syncthreads();
    }
}

// ---------------------------------------------------------------------------
// Kernel C: out = x * sel  (float4, bandwidth-bound)
// ---------------------------------------------------------------------------
__global__ __launch_bounds__(256)
void apply_kernel(const float* __restrict__ x, float* __restrict__ out)
{
    int i = blockIdx.x * blockDim.x + threadIdx.x;   // float4 index, exact grid
    float4 v = ((const float4*)x)[i];
    int frame = i >> 7;                              // 512/4 = 128 float4 per frame
    if (!g_sel[frame]) v = make_float4(0.f, 0.f, 0.f, 0.f);
    ((float4*)out)[i] = v;
}

// ---------------------------------------------------------------------------
extern "C" void kernel_launch(void* const* d_in, const int* in_sizes, int n_in,
                              void* d_out, int out_size)
{
    const float* x  = (const float*)d_in[0];
    const float* W1 = (const float*)d_in[1];
    const float* b1 = (const float*)d_in[2];
    const float* W2 = (const float*)d_in[3];
    const float* b2 = (const float*)d_in[4];
    float* out = (float*)d_out;

    score_kernel<<<NFRAMES / 64, 256>>>(x, W1, b1, W2, b2);
    topk_kernel<<<BATCH, 256>>>();
    int total4 = NFRAMES * FDIM / 4;                 // 8388608
    apply_kernel<<<total4 / 256, 256>>>(x, out);
}

// round 2
// speedup vs baseline: 1.3027x; 1.3027x over previous
#include <cuda_runtime.h>
#include <float.h>

// Problem constants (fixed shapes per reference)
#define BATCH   32
#define TLEN    2048
#define FDIM    512
#define UDIM    128
#define KSEL    64
#define NFRAMES (BATCH * TLEN)     // 65536
#define NEG_BIG -1.0e9f

// Scratch (no allocations allowed in kernel_launch)
__device__ float         g_scores[NFRAMES];
__device__ unsigned char g_sel[NFRAMES];

// ---------------------------------------------------------------------------
// Kernel A: fused score GEMM, 128x128 block tile, 8x8 register tile,
// double-buffered smem, A stored transposed for LDS.128 on both operands.
// Epilogue computes score = relu(h+b1).W2 + b2 with a 16-lane shfl reduce.
// ---------------------------------------------------------------------------
__global__ __launch_bounds__(256, 2)
void score_kernel(const float* __restrict__ x,
                  const float* __restrict__ W1,
                  const float* __restrict__ b1,
                  const float* __restrict__ W2,
                  const float* __restrict__ b2)
{
    __shared__ float As[2][16][132];   // [k][m], row stride 132 floats (528B, 16B-aligned)
    __shared__ float Bs[2][16][128];   // [k][n]
    __shared__ float s_b1[UDIM];
    __shared__ float s_W2[UDIM];
    __shared__ unsigned char rowNZ[128];

    const int tid = threadIdx.x;
    const int tx  = tid & 15;          // N direction (16 threads x 8 cols)
    const int ty  = tid >> 4;          // M direction (16 groups x 8 rows)
    const int frame0 = blockIdx.x * 128;

    if (tid < UDIM) {
        s_b1[tid]  = b1[tid];
        s_W2[tid]  = W2[tid];
        rowNZ[tid] = 0;
    }

    // Global->smem load mapping
    const int am = tid >> 2;           // A row within tile, 0..63 (and +64)
    const int ak = (tid & 3) * 4;      // A k offset, {0,4,8,12}
    const int bk = tid >> 5;           // B k row, 0..7 (and +8)
    const int bn = (tid & 31) * 4;     // B col offset

    const float* xA0 = x  + (size_t)(frame0 + am)      * FDIM + ak;
    const float* xA1 = x  + (size_t)(frame0 + am + 64) * FDIM + ak;
    const float* wB0 = W1 + (size_t)bk       * UDIM + bn;
    const float* wB1 = W1 + (size_t)(bk + 8) * UDIM + bn;

    float acc[8][8];
    #pragma unroll
    for (int i = 0; i < 8; i++)
        #pragma unroll
        for (int j = 0; j < 8; j++)
            acc[i][j] = 0.0f;

    bool nz0 = false, nz1 = false;

    // ---- prologue: chunk 0 ----
    float4 va0 = *(const float4*)xA0;
    float4 va1 = *(const float4*)xA1;
    float4 vb0 = *(const float4*)wB0;
    float4 vb1 = *(const float4*)wB1;

    nz0 |= (va0.x != 0.f) | (va0.y != 0.f) | (va0.z != 0.f) | (va0.w != 0.f);
    nz1 |= (va1.x != 0.f) | (va1.y != 0.f) | (va1.z != 0.f) | (va1.w != 0.f);
    As[0][ak + 0][am]      = va0.x; As[0][ak + 1][am]      = va0.y;
    As[0][ak + 2][am]      = va0.z; As[0][ak + 3][am]      = va0.w;
    As[0][ak + 0][am + 64] = va1.x; As[0][ak + 1][am + 64] = va1.y;
    As[0][ak + 2][am + 64] = va1.z; As[0][ak + 3][am + 64] = va1.w;
    *(float4*)&Bs[0][bk][bn]     = vb0;
    *(float4*)&Bs[0][bk + 8][bn] = vb1;
    __syncthreads();

    // ---- main loop over 32 k-chunks of 16 ----
    for (int c = 0; c < 32; c++) {
        const int cur = c & 1;
        const int nxt = cur ^ 1;

        if (c < 31) {
            const int ko = (c + 1) * 16;
            va0 = *(const float4*)(xA0 + ko);
            va1 = *(const float4*)(xA1 + ko);
            vb0 = *(const float4*)(wB0 + (size_t)ko * UDIM);
            vb1 = *(const float4*)(wB1 + (size_t)ko * UDIM);
        }

        #pragma unroll
        for (int kk = 0; kk < 16; kk++) {
            float4 a0 = *(const float4*)&As[cur][kk][ty * 8];
            float4 a1 = *(const float4*)&As[cur][kk][ty * 8 + 4];
            float4 bA = *(const float4*)&Bs[cur][kk][tx * 8];
            float4 bB = *(const float4*)&Bs[cur][kk][tx * 8 + 4];
            float a[8] = {a0.x, a0.y, a0.z, a0.w, a1.x, a1.y, a1.z, a1.w};
            float b[8] = {bA.x, bA.y, bA.z, bA.w, bB.x, bB.y, bB.z, bB.w};
            #pragma unroll
            for (int i = 0; i < 8; i++)
                #pragma unroll
                for (int j = 0; j < 8; j++)
                    acc[i][j] = fmaf(a[i], b[j], acc[i][j]);
        }

        if (c < 31) {
            nz0 |= (va0.x != 0.f) | (va0.y != 0.f) | (va0.z != 0.f) | (va0.w != 0.f);
            nz1 |= (va1.x != 0.f) | (va1.y != 0.f) | (va1.z != 0.f) | (va1.w != 0.f);
            As[nxt][ak + 0][am]      = va0.x; As[nxt][ak + 1][am]      = va0.y;
            As[nxt][ak + 2][am]      = va0.z; As[nxt][ak + 3][am]      = va0.w;
            As[nxt][ak + 0][am + 64] = va1.x; As[nxt][ak + 1][am + 64] = va1.y;
            As[nxt][ak + 2][am + 64] = va1.z; As[nxt][ak + 3][am + 64] = va1.w;
            *(float4*)&Bs[nxt][bk][bn]     = vb0;
            *(float4*)&Bs[nxt][bk + 8][bn] = vb1;
            __syncthreads();
        }
    }

    // publish nonzero-row flags (benign races: all writers store 1)
    if (nz0) rowNZ[am]      = 1;
    if (nz1) rowNZ[am + 64] = 1;
    __syncthreads();

    // ---- epilogue: score[row] = sum_n relu(h + b1[n]) * W2[n] + b2 ----
    const float bias2 = b2[0];
    #pragma unroll
    for (int i = 0; i < 8; i++) {
        float partial = 0.0f;
        #pragma unroll
        for (int j = 0; j < 8; j++) {
            const int n = tx * 8 + j;
            float h = acc[i][j] + s_b1[n];
            h = fmaxf(h, 0.0f);
            partial = fmaf(h, s_W2[n], partial);
        }
        #pragma unroll
        for (int off = 8; off >= 1; off >>= 1)
            partial += __shfl_xor_sync(0xffffffffu, partial, off, 16);
        if (tx == 0) {
            const int row = ty * 8 + i;
            float s = partial + bias2;
            if (!rowNZ[row]) s = NEG_BIG;
            g_scores[frame0 + row] = s;
        }
    }
}

// ---------------------------------------------------------------------------
// Kernel B: per-batch top-64 via 64 stable argmax passes (lowest-index ties,
// matching jax.lax.top_k's selected set). One block per batch row.
// ---------------------------------------------------------------------------
__global__ __launch_bounds__(256)
void topk_kernel()
{
    __shared__ float vals[TLEN];
    __shared__ float rv[256];
    __shared__ int   ri[256];

    const int b   = blockIdx.x;
    const int tid = threadIdx.x;
    const int base = b * TLEN;

    for (int i = tid; i < TLEN; i += 256) {
        vals[i] = g_scores[base + i];
        g_sel[base + i] = 0;
    }
    __syncthreads();

    for (int iter = 0; iter < KSEL; iter++) {
        float best = -FLT_MAX;
        int   bi   = TLEN;
        for (int i = tid; i < TLEN; i += 256) {
            float v = vals[i];
            if (v > best) { best = v; bi = i; }     // strided scan: first hit is lowest idx
        }
        rv[tid] = best; ri[tid] = bi;
        __syncthreads();
        #pragma unroll
        for (int s = 128; s >= 1; s >>= 1) {
            if (tid < s) {
                float ov = rv[tid + s]; int oi = ri[tid + s];
                if (ov > rv[tid] || (ov == rv[tid] && oi < ri[tid])) {
                    rv[tid] = ov; ri[tid] = oi;
                }
            }
            __syncthreads();
        }
        if (tid == 0) {
            int sel = ri[0];
            vals[sel] = -FLT_MAX;
            g_sel[base + sel] = 1;
        }
        __syncthreads();
    }
}

// ---------------------------------------------------------------------------
// Kernel C: out = x * sel  (float4, bandwidth-bound)
// ---------------------------------------------------------------------------
__global__ __launch_bounds__(256)
void apply_kernel(const float* __restrict__ x, float* __restrict__ out)
{
    int i = blockIdx.x * blockDim.x + threadIdx.x;   // float4 index, exact grid
    float4 v = ((const float4*)x)[i];
    int frame = i >> 7;                              // 512/4 = 128 float4 per frame
    if (!g_sel[frame]) v = make_float4(0.f, 0.f, 0.f, 0.f);
    ((float4*)out)[i] = v;
}

// ---------------------------------------------------------------------------
extern "C" void kernel_launch(void* const* d_in, const int* in_sizes, int n_in,
                              void* d_out, int out_size)
{
    const float* x  = (const float*)d_in[0];
    const float* W1 = (const float*)d_in[1];
    const float* b1 = (const float*)d_in[2];
    const float* W2 = (const float*)d_in[3];
    const float* b2 = (const float*)d_in[4];
    float* out = (float*)d_out;

    score_kernel<<<NFRAMES / 128, 256>>>(x, W1, b1, W2, b2);
    topk_kernel<<<BATCH, 256>>>();
    int total4 = NFRAMES * FDIM / 4;                 // 8388608
    apply_kernel<<<total4 / 256, 256>>>(x, out);
}

// round 5
// speedup vs baseline: 2.2675x; 1.7406x over previous
#include <cuda_runtime.h>
#include <cuda_bf16.h>
#include <float.h>
#include <stdint.h>

// Problem constants
#define BATCH   32
#define TLEN    2048
#define FDIM    512
#define UDIM    128
#define KSEL    64
#define NFRAMES (BATCH * TLEN)     // 65536
#define NEG_BIG -1.0e9f

// GEMM tiling
#define CHUNK     64                 // k elems per chunk
#define NCHUNK    (FDIM / CHUNK)     // 8
#define STRW      36                 // smem row stride in 32-bit words (144B): bank 4r+kp
#define TILE_W    (128 * STRW)       // words per tile (4608)
#define OFF_AH    0
#define OFF_AL    TILE_W
#define OFF_BH    (2 * TILE_W)
#define OFF_BL    (3 * TILE_W)
#define DYN_SMEM  (4 * TILE_W * 4)   // 73728 bytes

// Scratch (no allocations allowed)
__device__ float          g_scores[NFRAMES];
__device__ unsigned char  g_sel[NFRAMES];
__device__ __nv_bfloat16  g_Bhi[UDIM * FDIM];   // W1^T hi, [n][k]
__device__ __nv_bfloat16  g_Blo[UDIM * FDIM];   // W1^T lo

// ---------------------------------------------------------------------------
// helpers
// ---------------------------------------------------------------------------
// pack two fp32 -> bf16x2, 'lo' in low 16 bits
__device__ __forceinline__ uint32_t bf2(float lo, float hi) {
    uint32_t r;
    asm("cvt.rn.bf16x2.f32 %0, %1, %2;" : "=r"(r) : "f"(hi), "f"(lo));
    return r;
}
__device__ __forceinline__ void mma16816(float c[4],
                                         uint32_t a0, uint32_t a1, uint32_t a2, uint32_t a3,
                                         uint32_t b0, uint32_t b1) {
    asm("mma.sync.aligned.m16n8k16.row.col.f32.bf16.bf16.f32 "
        "{%0,%1,%2,%3}, {%4,%5,%6,%7}, {%8,%9}, {%0,%1,%2,%3};"
        : "+f"(c[0]), "+f"(c[1]), "+f"(c[2]), "+f"(c[3])
        : "r"(a0), "r"(a1), "r"(a2), "r"(a3), "r"(b0), "r"(b1));
}

// ---------------------------------------------------------------------------
// Prep: split W1 [F,U] into bf16 hi/lo, transposed to [N=U][K=F]
// ---------------------------------------------------------------------------
__global__ __launch_bounds__(256)
void prep_kernel(const float* __restrict__ W1)
{
    int id = blockIdx.x * 256 + threadIdx.x;   // 0 .. 65535
    int n = id >> 9;                           // 0..127
    int k = id & 511;                          // 0..511
    float v = W1[(size_t)k * UDIM + n];
    __nv_bfloat16 h = __float2bfloat16(v);
    g_Bhi[n * FDIM + k] = h;
    g_Blo[n * FDIM + k] = __float2bfloat16(v - __bfloat162float(h));
}

// ---------------------------------------------------------------------------
// Score GEMM: mma.sync bf16x3 (hi*hi + hi*lo + lo*hi), fp32 accum in regs.
// CTA tile 128x128, 8 warps in 4(m) x 2(n), warp tile 32x64.
// ---------------------------------------------------------------------------
extern __shared__ uint32_t dynw[];

__global__ __launch_bounds__(256, 2)
void score_kernel(const float* __restrict__ x,
                  const float* __restrict__ b1,
                  const float* __restrict__ W2,
                  const float* __restrict__ b2)
{
    __shared__ float s_b1[UDIM], s_W2[UDIM];
    __shared__ float s_part[2][128];
    __shared__ unsigned char s_nz[128];

    const int tid  = threadIdx.x;
    const int wid  = tid >> 5;
    const int lane = tid & 31;
    const int mw   = wid & 3;          // m-warp 0..3 (rows mw*32..+31)
    const int nw   = wid >> 2;         // n-warp 0..1 (cols nw*64..+63)
    const int g    = lane >> 2;        // group row 0..7
    const int tig  = lane & 3;         // thread-in-group
    const int frame0 = blockIdx.x * 128;

    if (tid < UDIM) { s_b1[tid] = b1[tid]; s_W2[tid] = W2[tid]; s_nz[tid] = 0; }

    // load/store mapping: 2 threads per row, 32 elems each
    const int row  = tid >> 1;
    const int half = tid & 1;
    const float*         xrow = x + (size_t)(frame0 + row) * FDIM + half * 32;
    const __nv_bfloat16* bhr  = g_Bhi + row * FDIM + half * 32;
    const __nv_bfloat16* blr  = g_Blo + row * FDIM + half * 32;
    const int stw = row * STRW + half * 16;    // word offset of this thread's 16-word span

    float acc[2][8][4];
    #pragma unroll
    for (int ma = 0; ma < 2; ma++)
        #pragma unroll
        for (int nb = 0; nb < 8; nb++)
            #pragma unroll
            for (int i = 0; i < 4; i++)
                acc[ma][nb][i] = 0.0f;

    bool nz = false;

    for (int c = 0; c < NCHUNK; c++) {
        const int kc = c * CHUNK;

        // ---- x -> Ahi/Alo (split in registers), v4 stores (conflict-free) ----
        #pragma unroll
        for (int j = 0; j < 4; j++) {
            float4 v0 = *(const float4*)(xrow + kc + j * 8);
            float4 v1 = *(const float4*)(xrow + kc + j * 8 + 4);
            nz |= (v0.x != 0.f) | (v0.y != 0.f) | (v0.z != 0.f) | (v0.w != 0.f)
                | (v1.x != 0.f) | (v1.y != 0.f) | (v1.z != 0.f) | (v1.w != 0.f);
            uint32_t h0 = bf2(v0.x, v0.y);
            uint32_t h1 = bf2(v0.z, v0.w);
            uint32_t h2 = bf2(v1.x, v1.y);
            uint32_t h3 = bf2(v1.z, v1.w);
            float r0 = v0.x - __uint_as_float(h0 << 16);
            float r1 = v0.y - __uint_as_float(h0 & 0xFFFF0000u);
            float r2 = v0.z - __uint_as_float(h1 << 16);
            float r3 = v0.w - __uint_as_float(h1 & 0xFFFF0000u);
            float r4 = v1.x - __uint_as_float(h2 << 16);
            float r5 = v1.y - __uint_as_float(h2 & 0xFFFF0000u);
            float r6 = v1.z - __uint_as_float(h3 << 16);
            float r7 = v1.w - __uint_as_float(h3 & 0xFFFF0000u);
            *(uint4*)&dynw[OFF_AH + stw + 4 * j] =
                make_uint4(h0, h1, h2, h3);
            *(uint4*)&dynw[OFF_AL + stw + 4 * j] =
                make_uint4(bf2(r0, r1), bf2(r2, r3), bf2(r4, r5), bf2(r6, r7));
        }
        // ---- W1^T hi/lo tiles (already bf16): straight copies ----
        #pragma unroll
        for (int j = 0; j < 4; j++) {
            uint4 wh = *(const uint4*)(bhr + kc + j * 8);
            uint4 wl = *(const uint4*)(blr + kc + j * 8);
            *(uint4*)&dynw[OFF_BH + stw + 4 * j] = wh;
            *(uint4*)&dynw[OFF_BL + stw + 4 * j] = wl;
        }
        __syncthreads();

        // ---- compute: 4 k16 steps ----
        #pragma unroll
        for (int ks = 0; ks < 4; ks++) {
            const int wk = ks * 8 + tig;
            const int ra0 = (mw * 32 + g) * STRW;          // ma=0 row base
            const int ra1 = ra0 + 16 * STRW;               // ma=1

            uint32_t ah0[4], ah1[4], al0[4], al1[4];
            ah0[0] = dynw[OFF_AH + ra0 + wk];
            ah0[1] = dynw[OFF_AH + ra0 + 8 * STRW + wk];
            ah0[2] = dynw[OFF_AH + ra0 + wk + 4];
            ah0[3] = dynw[OFF_AH + ra0 + 8 * STRW + wk + 4];
            ah1[0] = dynw[OFF_AH + ra1 + wk];
            ah1[1] = dynw[OFF_AH + ra1 + 8 * STRW + wk];
            ah1[2] = dynw[OFF_AH + ra1 + wk + 4];
            ah1[3] = dynw[OFF_AH + ra1 + 8 * STRW + wk + 4];
            al0[0] = dynw[OFF_AL + ra0 + wk];
            al0[1] = dynw[OFF_AL + ra0 + 8 * STRW + wk];
            al0[2] = dynw[OFF_AL + ra0 + wk + 4];
            al0[3] = dynw[OFF_AL + ra0 + 8 * STRW + wk + 4];
            al1[0] = dynw[OFF_AL + ra1 + wk];
            al1[1] = dynw[OFF_AL + ra1 + 8 * STRW + wk];
            al1[2] = dynw[OFF_AL + ra1 + wk + 4];
            al1[3] = dynw[OFF_AL + ra1 + 8 * STRW + wk + 4];

            #pragma unroll
            for (int nb = 0; nb < 8; nb++) {
                const int rb = (nw * 64 + nb * 8 + g) * STRW;
                uint32_t bh0 = dynw[OFF_BH + rb + wk];
                uint32_t bh1 = dynw[OFF_BH + rb + wk + 4];
                mma16816(acc[0][nb], ah0[0], ah0[1], ah0[2], ah0[3], bh0, bh1);
                mma16816(acc[1][nb], ah1[0], ah1[1], ah1[2], ah1[3], bh0, bh1);
                mma16816(acc[0][nb], al0[0], al0[1], al0[2], al0[3], bh0, bh1);
                mma16816(acc[1][nb], al1[0], al1[1], al1[2], al1[3], bh0, bh1);
                uint32_t bl0 = dynw[OFF_BL + rb + wk];
                uint32_t bl1 = dynw[OFF_BL + rb + wk + 4];
                mma16816(acc[0][nb], ah0[0], ah0[1], ah0[2], ah0[3], bl0, bl1);
                mma16816(acc[1][nb], ah1[0], ah1[1], ah1[2], ah1[3], bl0, bl1);
            }
        }
        __syncthreads();   // WAR before next chunk's stores
    }

    if (nz) s_nz[row] = 1;   // benign race (both halves store 1)

    // ---- epilogue: per-row score = sum_n relu(h + b1[n]) * W2[n] ----
    float p[2][2] = {{0.f, 0.f}, {0.f, 0.f}};   // [ma][row / row+8]
    #pragma unroll
    for (int ma = 0; ma < 2; ma++) {
        #pragma unroll
        for (int nb = 0; nb < 8; nb++) {
            const int n0 = nw * 64 + nb * 8 + 2 * tig;
            const int n1 = n0 + 1;
            float h;
            h = fmaxf(acc[ma][nb][0] + s_b1[n0], 0.f); p[ma][0] = fmaf(h, s_W2[n0], p[ma][0]);
            h = fmaxf(acc[ma][nb][1] + s_b1[n1], 0.f); p[ma][0] = fmaf(h, s_W2[n1], p[ma][0]);
            h = fmaxf(acc[ma][nb][2] + s_b1[n0], 0.f); p[ma][1] = fmaf(h, s_W2[n0], p[ma][1]);
            h = fmaxf(acc[ma][nb][3] + s_b1[n1], 0.f); p[ma][1] = fmaf(h, s_W2[n1], p[ma][1]);
        }
        // reduce over the 4 lanes of this group (width-4 segments)
        #pragma unroll
        for (int off = 2; off >= 1; off >>= 1) {
            p[ma][0] += __shfl_down_sync(0xffffffffu, p[ma][0], off, 4);
            p[ma][1] += __shfl_down_sync(0xffffffffu, p[ma][1], off, 4);
        }
    }
    if (tig == 0) {
        #pragma unroll
        for (int ma = 0; ma < 2; ma++) {
            const int r0 = mw * 32 + ma * 16 + g;
            s_part[nw][r0]     = p[ma][0];
            s_part[nw][r0 + 8] = p[ma][1];
        }
    }
    __syncthreads();

    if (tid < 128) {
        float s = s_part[0][tid] + s_part[1][tid] + b2[0];
        if (!s_nz[tid]) s = NEG_BIG;
        g_scores[frame0 + tid] = s;
    }
}

// ---------------------------------------------------------------------------
// Top-64 per batch: 64 stable argmax passes, warp-shuffle reduced
// ---------------------------------------------------------------------------
__global__ __launch_bounds__(256)
void topk_kernel()
{
    __shared__ float vals[TLEN];
    __shared__ float wv[8];
    __shared__ int   wi[8];

    const int b = blockIdx.x, tid = threadIdx.x;
    const int lane = tid & 31, w = tid >> 5;
    const int base = b * TLEN;

    for (int i = tid; i < TLEN; i += 256) {
        vals[i] = g_scores[base + i];
        g_sel[base + i] = 0;
    }
    __syncthreads();

    for (int it = 0; it < KSEL; it++) {
        float best = -FLT_MAX; int bi = TLEN;
        #pragma unroll
        for (int r = 0; r < 8; r++) {
            int i = tid + r * 256;
            float v = vals[i];
            if (v > best) { best = v; bi = i; }   // ascending i: first hit = lowest idx
        }
        #pragma unroll
        for (int off = 16; off >= 1; off >>= 1) {
            float ov = __shfl_down_sync(0xffffffffu, best, off);
            int   oi = __shfl_down_sync(0xffffffffu, bi, off);
            if (ov > best || (ov == best && oi < bi)) { best = ov; bi = oi; }
        }
        if (lane == 0) { wv[w] = best; wi[w] = bi; }
        __syncthreads();
        if (tid == 0) {
            float B = wv[0]; int I = wi[0];
            #pragma unroll
            for (int j = 1; j < 8; j++)
                if (wv[j] > B || (wv[j] == B && wi[j] < I)) { B = wv[j]; I = wi[j]; }
            vals[I] = -FLT_MAX;
            g_sel[base + I] = 1;
        }
        __syncthreads();
    }
}

// ---------------------------------------------------------------------------
// Apply: out = sel ? x : 0  (reads x only for selected frames)
// ---------------------------------------------------------------------------
__global__ __launch_bounds__(256)
void apply_kernel(const float* __restrict__ x, float* __restrict__ out)
{
    int i = blockIdx.x * 256 + threadIdx.x;      // float4 index
    int frame = i >> 7;                          // 128 float4 per frame
    float4 v = make_float4(0.f, 0.f, 0.f, 0.f);
    if (g_sel[frame]) v = ((const float4*)x)[i];
    ((float4*)out)[i] = v;
}

// ---------------------------------------------------------------------------
extern "C" void kernel_launch(void* const* d_in, const int* in_sizes, int n_in,
                              void* d_out, int out_size)
{
    (void)in_sizes; (void)n_in; (void)out_size;
    const float* x  = (const float*)d_in[0];
    const float* W1 = (const float*)d_in[1];
    const float* b1 = (const float*)d_in[2];
    const float* W2 = (const float*)d_in[3];
    const float* b2 = (const float*)d_in[4];
    float* out = (float*)d_out;

    cudaFuncSetAttribute(score_kernel,
                         cudaFuncAttributeMaxDynamicSharedMemorySize, DYN_SMEM);

    prep_kernel<<<256, 256>>>(W1);
    score_kernel<<<NFRAMES / 128, 256, DYN_SMEM>>>(x, b1, W2, b2);
    topk_kernel<<<BATCH, 256>>>();
    apply_kernel<<<NFRAMES * FDIM / 4 / 256, 256>>>(x, out);
}